// round 12
// baseline (speedup 1.0000x reference)
#include <cuda_runtime.h>
#include <cuda_bf16.h>
#include <cstdint>

#define N_NODES 100000
#define N_EDGES 1600000
#define NF 64
#define SCAN_BLOCKS 196           // ceil(100000/512)
#define GBLK 782                  // ceil(100000/128)
#define GEMM_SMEM 65536           // 128x128 A + 2x(128x64) W, bf16

// ---------------- scratch (static __device__ — no allocations allowed) ----------------
__device__ __nv_bfloat162 g_xbf [(size_t)N_NODES * 32];
__device__ __nv_bfloat162 g_aggr[(size_t)N_NODES * 32];
__device__ __nv_bfloat162 g_h1  [(size_t)N_NODES * 32];
__device__ __nv_bfloat16  g_whi [2 * 128 * 64];
__device__ __nv_bfloat16  g_wlo [2 * 128 * 64];
__device__ int   g_csr[N_EDGES];
__device__ int   g_indeg[N_NODES];
__device__ int   g_outdeg[N_NODES];
__device__ int   g_rowtmp[N_NODES];
__device__ int   g_rowptr[N_NODES + 1];
__device__ int   g_cursor[N_NODES];
__device__ int   g_bsum[256];
__device__ double g_red[1];
__device__ unsigned int g_cnt[1];
__device__ int   g_is64[1];

static __device__ __forceinline__ uint32_t su32(const void* p) {
    return (uint32_t)__cvta_generic_to_shared(p);
}

// ---------------- detect dtype (block 0) + zero indeg/outdeg/red/cnt -----------------
__global__ void __launch_bounds__(256) detect_zero_kernel(
    const unsigned int* __restrict__ w, int* __restrict__ flag,
    int* __restrict__ indeg, int* __restrict__ outdeg, double* __restrict__ red,
    unsigned int* __restrict__ cnt) {
    int i = blockIdx.x * 256 + threadIdx.x;
    if (i < N_NODES) { indeg[i] = 0; outdeg[i] = 0; }
    if (i == 0) { red[0] = 0.0; cnt[0] = 0u; }
    if (blockIdx.x == 0 && threadIdx.x < 64) {
        // int64 layout => every odd 32-bit word is the (zero) high half of a small id.
        unsigned int idx = 2u * (unsigned int)(threadIdx.x * 24999 + 13) + 1u;
        unsigned int v = w[idx];
        #pragma unroll
        for (int off = 16; off; off >>= 1)
            v |= __shfl_xor_sync(0xffffffffu, v, off);
        __shared__ unsigned int s0, s1;
        if (threadIdx.x == 0)  s0 = v;
        if (threadIdx.x == 32) s1 = v;
        __syncthreads();
        if (threadIdx.x == 0) *flag = ((s0 | s1) == 0u) ? 1 : 0;
    }
}

// ---------------- fused: degree hist + x->bf16 + weight hi/lo split ----------------
__global__ void __launch_bounds__(256) histconv_kernel(
    const void* __restrict__ ei, const float* __restrict__ x,
    __nv_bfloat162* __restrict__ xbf, int* __restrict__ indeg,
    int* __restrict__ outdeg, const int* __restrict__ flag,
    const float* __restrict__ wrel1, const float* __restrict__ wroot1,
    const float* __restrict__ wrel2, const float* __restrict__ wroot2,
    __nv_bfloat16* __restrict__ whi, __nv_bfloat16* __restrict__ wlo) {
    int idx = blockIdx.x * 256 + threadIdx.x;
    if (idx < (N_NODES * NF) / 8) {          // one uint4 of bf16 out per thread
        const float4* xs = (const float4*)x;
        float4 v0 = xs[2 * idx], v1 = xs[2 * idx + 1];
        __align__(16) __nv_bfloat162 o[4];
        o[0] = __float22bfloat162_rn(make_float2(v0.x, v0.y));
        o[1] = __float22bfloat162_rn(make_float2(v0.z, v0.w));
        o[2] = __float22bfloat162_rn(make_float2(v1.x, v1.y));
        o[3] = __float22bfloat162_rn(make_float2(v1.z, v1.w));
        reinterpret_cast<uint4*>(xbf)[idx] = *reinterpret_cast<uint4*>(o);
    }
    if (idx < 2 * 128 * 64) {                // weight hi/lo split
        int layer = idx >> 13;
        int rem = idx & 8191;
        int k = rem >> 6;
        int nn = rem & 63;
        const float* src = layer ? (k < 64 ? wrel2 : wroot2) : (k < 64 ? wrel1 : wroot1);
        float w = src[(k & 63) * 64 + nn];
        __nv_bfloat16 hi = __float2bfloat16(w);
        __nv_bfloat16 lo = __float2bfloat16(w - __bfloat162float(hi));
        whi[idx] = hi;
        wlo[idx] = lo;
    }
    if (idx < N_EDGES) {
        int s, d;
        if (*flag) {
            const long long* p = (const long long*)ei;
            s = (int)p[idx];
            d = (int)p[N_EDGES + idx];
        } else {
            const int* p = (const int*)ei;
            s = p[idx];
            d = p[N_EDGES + idx];
        }
        atomicAdd(indeg + d, 1);
        atomicAdd(outdeg + s, 1);
    }
}

// ---------------- scan: block-local inclusive scan (shuffle) ----------------
__global__ void scan1_kernel(const int* __restrict__ indeg, int* __restrict__ rowtmp,
                             int* __restrict__ bsum) {
    __shared__ int warpsum[16];
    int tid = threadIdx.x;
    int i = blockIdx.x * 512 + tid;
    int v = (i < N_NODES) ? indeg[i] : 0;
    int lane = tid & 31, w = tid >> 5;
    #pragma unroll
    for (int off = 1; off < 32; off <<= 1) {
        int t = __shfl_up_sync(0xffffffffu, v, off);
        if (lane >= off) v += t;
    }
    if (lane == 31) warpsum[w] = v;
    __syncthreads();
    if (w == 0) {
        int s = (lane < 16) ? warpsum[lane] : 0;
        #pragma unroll
        for (int off = 1; off < 16; off <<= 1) {
            int t = __shfl_up_sync(0xffffffffu, s, off);
            if (lane >= off) s += t;
        }
        if (lane < 16) warpsum[lane] = s;
    }
    __syncthreads();
    if (w > 0) v += warpsum[w - 1];
    if (i < N_NODES) rowtmp[i] = v;
    if (tid == 511) bsum[blockIdx.x] = v;
}

// scan of block sums (redundant per block, shuffle) + apply -> rowptr, cursor
__global__ void scan23_kernel(const int* __restrict__ rowtmp, const int* __restrict__ bsum,
                              const int* __restrict__ indeg, int* __restrict__ rowptr,
                              int* __restrict__ cursor) {
    __shared__ int bs[256];
    __shared__ int wsum[8];
    int tid = threadIdx.x;
    int lane = tid & 31, w = tid >> 5;
    int v = (tid < SCAN_BLOCKS) ? bsum[tid] : 0;
    #pragma unroll
    for (int off = 1; off < 32; off <<= 1) {
        int t = __shfl_up_sync(0xffffffffu, v, off);
        if (lane >= off) v += t;
    }
    if (lane == 31) wsum[w] = v;
    __syncthreads();
    if (w == 0 && lane < 8) {
        int s = wsum[lane];
        #pragma unroll
        for (int off = 1; off < 8; off <<= 1) {
            int t = __shfl_up_sync(0xffu, s, off);
            if (lane >= off) s += t;
        }
        wsum[lane] = s;
    }
    __syncthreads();
    if (w > 0) v += wsum[w - 1];
    bs[tid] = v;                 // inclusive scan of block sums
    __syncthreads();

    int i = blockIdx.x * 256 + tid;
    if (i >= N_NODES) return;
    int b = i >> 9;
    int add = (b > 0) ? bs[b - 1] : 0;
    int inc = rowtmp[i] + add;
    rowptr[i + 1] = inc;
    cursor[i] = inc - indeg[i];
    if (i == 0) rowptr[0] = 0;
}

__global__ void fill_kernel(const void* __restrict__ ei, int* __restrict__ cursor,
                            int* __restrict__ csr, const int* __restrict__ flag) {
    int e = blockIdx.x * blockDim.x + threadIdx.x;
    if (e >= N_EDGES) return;
    int s, d;
    if (*flag) {
        const long long* p = (const long long*)ei;
        s = (int)p[e];
        d = (int)p[N_EDGES + e];
    } else {
        const int* p = (const int*)ei;
        s = p[e];
        d = p[N_EDGES + e];
    }
    int pos = atomicAdd(cursor + d, 1);
    csr[pos] = s;
}

// ---------------- aggregation: aggr[i] = sum_{j in N(i)} feat[j] (bf16) --------------
// one warp per node; 8 edges in flight; each 8-lane group loads a 128B row (LDG.128).
// bf16x2 accumulation (HADD2); per-lane chains are only deg/8 adds; f32 cross-group.
__global__ void __launch_bounds__(256) aggr_kernel(const __nv_bfloat162* __restrict__ feat,
                                                   __nv_bfloat162* __restrict__ aggr,
                                                   const int* __restrict__ rowptr,
                                                   const int* __restrict__ csr) {
    const int lane = threadIdx.x & 31;
    const int grp = lane >> 3;
    const int sub = lane & 7;
    const int node = blockIdx.x * 8 + (threadIdx.x >> 5);
    if (node >= N_NODES) return;
    const int beg = rowptr[node];
    const int end = rowptr[node + 1];

    __nv_bfloat162 acc[4];
    #pragma unroll
    for (int q = 0; q < 4; q++) acc[q] = __float2bfloat162_rn(0.f);

    for (int j = beg; j < end; j += 8) {
        int e0 = j + grp;
        int e1 = j + 4 + grp;
        if (e0 < end) {
            int s = __ldg(csr + e0);
            uint4 v = *reinterpret_cast<const uint4*>(feat + (size_t)s * 32 + sub * 4);
            acc[0] = __hadd2(acc[0], *(__nv_bfloat162*)&v.x);
            acc[1] = __hadd2(acc[1], *(__nv_bfloat162*)&v.y);
            acc[2] = __hadd2(acc[2], *(__nv_bfloat162*)&v.z);
            acc[3] = __hadd2(acc[3], *(__nv_bfloat162*)&v.w);
        }
        if (e1 < end) {
            int s = __ldg(csr + e1);
            uint4 v = *reinterpret_cast<const uint4*>(feat + (size_t)s * 32 + sub * 4);
            acc[0] = __hadd2(acc[0], *(__nv_bfloat162*)&v.x);
            acc[1] = __hadd2(acc[1], *(__nv_bfloat162*)&v.y);
            acc[2] = __hadd2(acc[2], *(__nv_bfloat162*)&v.z);
            acc[3] = __hadd2(acc[3], *(__nv_bfloat162*)&v.w);
        }
    }

    // cross-group reduce in f32 (lanes differing in bits 3,4)
    float2 f[4];
    #pragma unroll
    for (int q = 0; q < 4; q++) f[q] = __bfloat1622float2(acc[q]);
    #pragma unroll
    for (int q = 0; q < 4; q++) {
        f[q].x += __shfl_xor_sync(0xffffffffu, f[q].x, 8);
        f[q].y += __shfl_xor_sync(0xffffffffu, f[q].y, 8);
        f[q].x += __shfl_xor_sync(0xffffffffu, f[q].x, 16);
        f[q].y += __shfl_xor_sync(0xffffffffu, f[q].y, 16);
    }
    if (grp == 0) {
        __align__(16) __nv_bfloat162 ob[4];
        #pragma unroll
        for (int q = 0; q < 4; q++) ob[q] = __float22bfloat162_rn(f[q]);
        *reinterpret_cast<uint4*>(aggr + (size_t)node * 32 + sub * 4) =
            *reinterpret_cast<uint4*>(ob);
    }
}

// ---------------- tensor-core GEMM: act([A1|A2] @ (Whi+Wlo) + b) ---------------------
// Block: 128 rows x 64 cols, 256 threads (8 warps, 16 rows each). K = 128 (8 k-steps),
// mma.sync.m16n8k16 bf16, weights hi+lo split. 64KB dynamic smem (halves W reloads).
// mode 0: write relu(out). mode 1: fused collapsed layer-3 reduction + last-block
//         final writeout.
__global__ void __launch_bounds__(256) mma_gemm_kernel(
    const __nv_bfloat162* __restrict__ A1, const __nv_bfloat162* __restrict__ A2,
    const __nv_bfloat16* __restrict__ Whi, const __nv_bfloat16* __restrict__ Wlo,
    const float* __restrict__ bias, __nv_bfloat162* __restrict__ out,
    const int* __restrict__ outdeg, const float* __restrict__ wrel3,
    const float* __restrict__ wroot3, double* __restrict__ red,
    unsigned int* __restrict__ cnt, const float* __restrict__ b3,
    float* __restrict__ final_out, int mode) {
    extern __shared__ __align__(16) __nv_bfloat16 smem[];
    __nv_bfloat16* Ash  = smem;                  // 128 x 128 = 32KB
    __nv_bfloat16* Wsh0 = smem + 128 * 128;      // 128 x 64  = 16KB (hi)
    __nv_bfloat16* Wsh1 = Wsh0 + 128 * 64;       // 128 x 64  = 16KB (lo)

    const int tid = threadIdx.x;
    const int lane = tid & 31;
    const int warp = tid >> 5;
    const int row_base = blockIdx.x * 128;

    // load A tile: 128 rows x 128 k (A1 k0-63 chunks0-7, A2 k64-127 chunks8-15)
    {
        int r = tid & 127;
        int half = tid >> 7;
        int grow = row_base + r;
        if (grow >= N_NODES) grow = N_NODES - 1;
        const uint4* src = reinterpret_cast<const uint4*>(
            (half ? A2 : A1) + (size_t)grow * 32);
        #pragma unroll
        for (int q = 0; q < 8; q++) {
            uint4 v = src[q];
            int chunk = half * 8 + q;
            int sw = (chunk & 8) | ((chunk ^ r) & 7);
            *reinterpret_cast<uint4*>(Ash + r * 128 + sw * 8) = v;
        }
    }
    // load W hi/lo: 2 x 128 rows x 8 chunks = 2048 uint4
    {
        #pragma unroll
        for (int q = 0; q < 8; q++) {
            int lin = q * 256 + tid;             // 0..2047
            int hl = lin >> 10;
            int rem = lin & 1023;
            int r = rem >> 3;
            int c = rem & 7;
            uint4 v = reinterpret_cast<const uint4*>((hl ? Wlo : Whi) + r * 64)[c];
            int sw = c ^ (r & 7);
            *reinterpret_cast<uint4*>((hl ? Wsh1 : Wsh0) + r * 64 + sw * 8) = v;
        }
    }
    __syncthreads();

    float d[8][4];
    #pragma unroll
    for (int t = 0; t < 8; t++)
        #pragma unroll
        for (int q = 0; q < 4; q++) d[t][q] = 0.f;

    const int wrow = warp * 16;

    #pragma unroll
    for (int ks = 0; ks < 8; ks++) {
        uint32_t a0, a1, a2, a3;
        {
            int ar = wrow + (lane & 15);
            int ac = ks * 2 + (lane >> 4);
            int sw = (ac & 8) | ((ac ^ ar) & 7);
            uint32_t addr = su32(Ash + ar * 128 + sw * 8);
            asm volatile("ldmatrix.sync.aligned.m8n8.x4.shared.b16 {%0,%1,%2,%3}, [%4];"
                         : "=r"(a0), "=r"(a1), "=r"(a2), "=r"(a3) : "r"(addr));
        }
        #pragma unroll
        for (int hl = 0; hl < 2; hl++) {
            const __nv_bfloat16* Wb = hl ? Wsh1 : Wsh0;
            #pragma unroll
            for (int nt2 = 0; nt2 < 4; nt2++) {
                int krow = ks * 16 + (lane & 15);
                int c = nt2 * 2 + (lane >> 4);
                int sw = c ^ (krow & 7);
                uint32_t addr = su32(Wb + krow * 64 + sw * 8);
                uint32_t b0, b1, b2, b3r;
                asm volatile("ldmatrix.sync.aligned.m8n8.x4.trans.shared.b16 {%0,%1,%2,%3}, [%4];"
                             : "=r"(b0), "=r"(b1), "=r"(b2), "=r"(b3r) : "r"(addr));
                asm volatile("mma.sync.aligned.m16n8k16.row.col.f32.bf16.bf16.f32 "
                             "{%0,%1,%2,%3},{%4,%5,%6,%7},{%8,%9},{%0,%1,%2,%3};"
                             : "+f"(d[nt2 * 2][0]), "+f"(d[nt2 * 2][1]),
                               "+f"(d[nt2 * 2][2]), "+f"(d[nt2 * 2][3])
                             : "r"(a0), "r"(a1), "r"(a2), "r"(a3), "r"(b0), "r"(b1));
                asm volatile("mma.sync.aligned.m16n8k16.row.col.f32.bf16.bf16.f32 "
                             "{%0,%1,%2,%3},{%4,%5,%6,%7},{%8,%9},{%0,%1,%2,%3};"
                             : "+f"(d[nt2 * 2 + 1][0]), "+f"(d[nt2 * 2 + 1][1]),
                               "+f"(d[nt2 * 2 + 1][2]), "+f"(d[nt2 * 2 + 1][3])
                             : "r"(a0), "r"(a1), "r"(a2), "r"(a3), "r"(b2), "r"(b3r));
            }
        }
    }

    const int g = lane >> 2;
    const int tg = lane & 3;
    const int row0 = row_base + wrow + g;
    const int row1 = row0 + 8;

    if (mode == 0) {
        #pragma unroll
        for (int t = 0; t < 8; t++) {
            int col = 8 * t + 2 * tg;
            float2 bv = *reinterpret_cast<const float2*>(bias + col);
            float o0 = fmaxf(d[t][0] + bv.x, 0.f), o1 = fmaxf(d[t][1] + bv.y, 0.f);
            float o2 = fmaxf(d[t][2] + bv.x, 0.f), o3 = fmaxf(d[t][3] + bv.y, 0.f);
            if (row0 < N_NODES)
                out[(size_t)row0 * 32 + (col >> 1)] = __float22bfloat162_rn(make_float2(o0, o1));
            if (row1 < N_NODES)
                out[(size_t)row1 * 32 + (col >> 1)] = __float22bfloat162_rn(make_float2(o2, o3));
        }
    } else {
        // fused collapsed layer-3: sum_i outdeg[i]*(h2_i . wrel3) + (h2_i . wroot3)
        float r0rel = 0.f, r0root = 0.f, r1rel = 0.f, r1root = 0.f;
        #pragma unroll
        for (int t = 0; t < 8; t++) {
            int col = 8 * t + 2 * tg;
            float2 bv = *reinterpret_cast<const float2*>(bias + col);
            float o0 = fmaxf(d[t][0] + bv.x, 0.f), o1 = fmaxf(d[t][1] + bv.y, 0.f);
            float o2 = fmaxf(d[t][2] + bv.x, 0.f), o3 = fmaxf(d[t][3] + bv.y, 0.f);
            float2 wr = *reinterpret_cast<const float2*>(wrel3 + col);
            float2 wo = *reinterpret_cast<const float2*>(wroot3 + col);
            r0rel  += o0 * wr.x + o1 * wr.y;
            r0root += o0 * wo.x + o1 * wo.y;
            r1rel  += o2 * wr.x + o3 * wr.y;
            r1root += o2 * wo.x + o3 * wo.y;
        }
        #pragma unroll
        for (int off = 1; off <= 2; off <<= 1) {
            r0rel  += __shfl_xor_sync(0xffffffffu, r0rel,  off);
            r0root += __shfl_xor_sync(0xffffffffu, r0root, off);
            r1rel  += __shfl_xor_sync(0xffffffffu, r1rel,  off);
            r1root += __shfl_xor_sync(0xffffffffu, r1root, off);
        }
        float val = 0.f;
        if (tg == 0) {
            if (row0 < N_NODES) val += (float)__ldg(outdeg + row0) * r0rel + r0root;
            if (row1 < N_NODES) val += (float)__ldg(outdeg + row1) * r1rel + r1root;
        }
        val += __shfl_xor_sync(0xffffffffu, val, 4);
        val += __shfl_xor_sync(0xffffffffu, val, 8);
        val += __shfl_xor_sync(0xffffffffu, val, 16);
        if (lane == 0) atomicAdd(red, (double)val);

        // last-block final writeout
        __syncthreads();
        if (tid == 0) {
            __threadfence();
            unsigned int old = atomicInc(cnt, 0xffffffffu);
            if (old == (unsigned int)(gridDim.x - 1)) {
                double r = atomicAdd(red, 0.0);   // all contributions visible
                final_out[0] = (float)(r / (double)N_NODES + (double)b3[0]);
            }
        }
    }
}

// ---------------- launch ----------------
extern "C" void kernel_launch(void* const* d_in, const int* in_sizes, int n_in,
                              void* d_out, int out_size) {
    const float* x      = (const float*)d_in[0];
    const void*  ei     = d_in[1];
    const float* wrel1  = (const float*)d_in[2];
    const float* brel1  = (const float*)d_in[3];
    const float* wroot1 = (const float*)d_in[4];
    const float* wrel2  = (const float*)d_in[5];
    const float* brel2  = (const float*)d_in[6];
    const float* wroot2 = (const float*)d_in[7];
    const float* wrel3  = (const float*)d_in[8];
    const float* brel3  = (const float*)d_in[9];
    const float* wroot3 = (const float*)d_in[10];
    float* out = (float*)d_out;

    __nv_bfloat162 *xbf, *aggr, *h1;
    __nv_bfloat16 *whi, *wlo;
    int *csr, *indeg, *outdeg, *rowtmp, *rowptr, *cursor, *bsum, *is64;
    double* red;
    unsigned int* cnt;
    cudaGetSymbolAddress((void**)&xbf,    g_xbf);
    cudaGetSymbolAddress((void**)&aggr,   g_aggr);
    cudaGetSymbolAddress((void**)&h1,     g_h1);
    cudaGetSymbolAddress((void**)&whi,    g_whi);
    cudaGetSymbolAddress((void**)&wlo,    g_wlo);
    cudaGetSymbolAddress((void**)&csr,    g_csr);
    cudaGetSymbolAddress((void**)&indeg,  g_indeg);
    cudaGetSymbolAddress((void**)&outdeg, g_outdeg);
    cudaGetSymbolAddress((void**)&rowtmp, g_rowtmp);
    cudaGetSymbolAddress((void**)&rowptr, g_rowptr);
    cudaGetSymbolAddress((void**)&cursor, g_cursor);
    cudaGetSymbolAddress((void**)&bsum,   g_bsum);
    cudaGetSymbolAddress((void**)&red,    g_red);
    cudaGetSymbolAddress((void**)&cnt,    g_cnt);
    cudaGetSymbolAddress((void**)&is64,   g_is64);

    const int eblk = (N_EDGES + 255) / 256;     // 6250
    const int nblk = (N_NODES + 255) / 256;     // 391
    const int ablk = (N_NODES + 7) / 8;         // 12500

    static bool attr_set = false;
    if (!attr_set) {
        cudaFuncSetAttribute(mma_gemm_kernel,
                             cudaFuncAttributeMaxDynamicSharedMemorySize, GEMM_SMEM);
        attr_set = true;
    }

    // prep + CSR build (R10 structure — measured fastest)
    detect_zero_kernel<<<nblk, 256>>>((const unsigned int*)ei, is64, indeg, outdeg, red, cnt);
    histconv_kernel<<<eblk, 256>>>(ei, x, xbf, indeg, outdeg, is64,
                                   wrel1, wroot1, wrel2, wroot2, whi, wlo);
    scan1_kernel<<<SCAN_BLOCKS, 512>>>(indeg, rowtmp, bsum);
    scan23_kernel<<<nblk, 256>>>(rowtmp, bsum, indeg, rowptr, cursor);
    fill_kernel<<<eblk, 256>>>(ei, cursor, csr, is64);

    // layer 1
    aggr_kernel<<<ablk, 256>>>(xbf, aggr, rowptr, csr);
    mma_gemm_kernel<<<GBLK, 256, GEMM_SMEM>>>(aggr, xbf, whi, wlo, brel1, h1,
                                              nullptr, nullptr, nullptr, nullptr, nullptr,
                                              nullptr, nullptr, 0);
    // layer 2 (+ fused collapsed layer-3 reduction + last-block final writeout)
    aggr_kernel<<<ablk, 256>>>(h1, aggr, rowptr, csr);
    mma_gemm_kernel<<<GBLK, 256, GEMM_SMEM>>>(aggr, h1, whi + 8192, wlo + 8192, brel2, nullptr,
                                              outdeg, wrel3, wroot3, red, cnt, brel3, out, 1);
}

// round 13
// speedup vs baseline: 1.4088x; 1.4088x over previous
#include <cuda_runtime.h>
#include <cuda_bf16.h>
#include <cstdint>

#define N_NODES 100000
#define N_EDGES 1600000
#define NF 64
#define SCAN_BLOCKS 196           // ceil(100000/512)
#define GBLK 1563                 // ceil(100000/64)

// ---------------- scratch (static __device__ — no allocations allowed) ----------------
__device__ __nv_bfloat162 g_xbf [(size_t)N_NODES * 32];
__device__ __nv_bfloat162 g_aggr[(size_t)N_NODES * 32];
__device__ __nv_bfloat162 g_h1  [(size_t)N_NODES * 32];
__device__ __nv_bfloat16  g_whi [2 * 128 * 64];
__device__ __nv_bfloat16  g_wlo [2 * 128 * 64];
__device__ int   g_csr[N_EDGES];
__device__ int   g_indeg[N_NODES];
__device__ int   g_outdeg[N_NODES];
__device__ int   g_rowtmp[N_NODES];
__device__ int   g_rowptr[N_NODES + 1];
__device__ int   g_cursor[N_NODES];
__device__ int   g_bsum[256];
__device__ double g_red[1];
__device__ unsigned int g_cnt[1];
__device__ int   g_is64[1];

static __device__ __forceinline__ uint32_t su32(const void* p) {
    return (uint32_t)__cvta_generic_to_shared(p);
}

// ---------------- detect dtype (block 0) + zero indeg/outdeg/red/cnt -----------------
__global__ void __launch_bounds__(256) detect_zero_kernel(
    const unsigned int* __restrict__ w, int* __restrict__ flag,
    int* __restrict__ indeg, int* __restrict__ outdeg, double* __restrict__ red,
    unsigned int* __restrict__ cnt) {
    int i = blockIdx.x * 256 + threadIdx.x;
    if (i < N_NODES) { indeg[i] = 0; outdeg[i] = 0; }
    if (i == 0) { red[0] = 0.0; cnt[0] = 0u; }
    if (blockIdx.x == 0 && threadIdx.x < 64) {
        // int64 layout => every odd 32-bit word is the (zero) high half of a small id.
        unsigned int idx = 2u * (unsigned int)(threadIdx.x * 24999 + 13) + 1u;
        unsigned int v = w[idx];
        #pragma unroll
        for (int off = 16; off; off >>= 1)
            v |= __shfl_xor_sync(0xffffffffu, v, off);
        __shared__ unsigned int s0, s1;
        if (threadIdx.x == 0)  s0 = v;
        if (threadIdx.x == 32) s1 = v;
        __syncthreads();
        if (threadIdx.x == 0) *flag = ((s0 | s1) == 0u) ? 1 : 0;
    }
}

// ---------------- fused: degree hist + x->bf16 + weight hi/lo split ----------------
__global__ void __launch_bounds__(256) histconv_kernel(
    const void* __restrict__ ei, const float* __restrict__ x,
    __nv_bfloat162* __restrict__ xbf, int* __restrict__ indeg,
    int* __restrict__ outdeg, const int* __restrict__ flag,
    const float* __restrict__ wrel1, const float* __restrict__ wroot1,
    const float* __restrict__ wrel2, const float* __restrict__ wroot2,
    __nv_bfloat16* __restrict__ whi, __nv_bfloat16* __restrict__ wlo) {
    int idx = blockIdx.x * 256 + threadIdx.x;
    if (idx < (N_NODES * NF) / 8) {          // one uint4 of bf16 out per thread
        const float4* xs = (const float4*)x;
        float4 v0 = xs[2 * idx], v1 = xs[2 * idx + 1];
        __align__(16) __nv_bfloat162 o[4];
        o[0] = __float22bfloat162_rn(make_float2(v0.x, v0.y));
        o[1] = __float22bfloat162_rn(make_float2(v0.z, v0.w));
        o[2] = __float22bfloat162_rn(make_float2(v1.x, v1.y));
        o[3] = __float22bfloat162_rn(make_float2(v1.z, v1.w));
        reinterpret_cast<uint4*>(xbf)[idx] = *reinterpret_cast<uint4*>(o);
    }
    if (idx < 2 * 128 * 64) {                // weight hi/lo split
        int layer = idx >> 13;
        int rem = idx & 8191;
        int k = rem >> 6;
        int nn = rem & 63;
        const float* src = layer ? (k < 64 ? wrel2 : wroot2) : (k < 64 ? wrel1 : wroot1);
        float w = src[(k & 63) * 64 + nn];
        __nv_bfloat16 hi = __float2bfloat16(w);
        __nv_bfloat16 lo = __float2bfloat16(w - __bfloat162float(hi));
        whi[idx] = hi;
        wlo[idx] = lo;
    }
    if (idx < N_EDGES) {
        int s, d;
        if (*flag) {
            const long long* p = (const long long*)ei;
            s = (int)p[idx];
            d = (int)p[N_EDGES + idx];
        } else {
            const int* p = (const int*)ei;
            s = p[idx];
            d = p[N_EDGES + idx];
        }
        atomicAdd(indeg + d, 1);
        atomicAdd(outdeg + s, 1);
    }
}

// ---------------- scan: block-local inclusive scan (shuffle) ----------------
__global__ void scan1_kernel(const int* __restrict__ indeg, int* __restrict__ rowtmp,
                             int* __restrict__ bsum) {
    __shared__ int warpsum[16];
    int tid = threadIdx.x;
    int i = blockIdx.x * 512 + tid;
    int v = (i < N_NODES) ? indeg[i] : 0;
    int lane = tid & 31, w = tid >> 5;
    #pragma unroll
    for (int off = 1; off < 32; off <<= 1) {
        int t = __shfl_up_sync(0xffffffffu, v, off);
        if (lane >= off) v += t;
    }
    if (lane == 31) warpsum[w] = v;
    __syncthreads();
    if (w == 0) {
        int s = (lane < 16) ? warpsum[lane] : 0;
        #pragma unroll
        for (int off = 1; off < 16; off <<= 1) {
            int t = __shfl_up_sync(0xffffffffu, s, off);
            if (lane >= off) s += t;
        }
        if (lane < 16) warpsum[lane] = s;
    }
    __syncthreads();
    if (w > 0) v += warpsum[w - 1];
    if (i < N_NODES) rowtmp[i] = v;
    if (tid == 511) bsum[blockIdx.x] = v;
}

// scan of block sums (redundant per block, shuffle) + apply -> rowptr, cursor
__global__ void scan23_kernel(const int* __restrict__ rowtmp, const int* __restrict__ bsum,
                              const int* __restrict__ indeg, int* __restrict__ rowptr,
                              int* __restrict__ cursor) {
    __shared__ int bs[256];
    __shared__ int wsum[8];
    int tid = threadIdx.x;
    int lane = tid & 31, w = tid >> 5;
    int v = (tid < SCAN_BLOCKS) ? bsum[tid] : 0;
    #pragma unroll
    for (int off = 1; off < 32; off <<= 1) {
        int t = __shfl_up_sync(0xffffffffu, v, off);
        if (lane >= off) v += t;
    }
    if (lane == 31) wsum[w] = v;
    __syncthreads();
    if (w == 0 && lane < 8) {
        int s = wsum[lane];
        #pragma unroll
        for (int off = 1; off < 8; off <<= 1) {
            int t = __shfl_up_sync(0xffu, s, off);
            if (lane >= off) s += t;
        }
        wsum[lane] = s;
    }
    __syncthreads();
    if (w > 0) v += wsum[w - 1];
    bs[tid] = v;                 // inclusive scan of block sums
    __syncthreads();

    int i = blockIdx.x * 256 + tid;
    if (i >= N_NODES) return;
    int b = i >> 9;
    int add = (b > 0) ? bs[b - 1] : 0;
    int inc = rowtmp[i] + add;
    rowptr[i + 1] = inc;
    cursor[i] = inc - indeg[i];
    if (i == 0) rowptr[0] = 0;
}

__global__ void fill_kernel(const void* __restrict__ ei, int* __restrict__ cursor,
                            int* __restrict__ csr, const int* __restrict__ flag) {
    int e = blockIdx.x * blockDim.x + threadIdx.x;
    if (e >= N_EDGES) return;
    int s, d;
    if (*flag) {
        const long long* p = (const long long*)ei;
        s = (int)p[e];
        d = (int)p[N_EDGES + e];
    } else {
        const int* p = (const int*)ei;
        s = p[e];
        d = p[N_EDGES + e];
    }
    int pos = atomicAdd(cursor + d, 1);
    csr[pos] = s;
}

// ---------------- aggregation: aggr[i] = sum_{j in N(i)} feat[j] (bf16) --------------
// one warp per node; 8 edges in flight; each 8-lane group loads a 128B row (LDG.128).
// bf16x2 accumulation (HADD2); per-lane chains are only deg/8 adds; f32 cross-group.
__global__ void __launch_bounds__(256) aggr_kernel(const __nv_bfloat162* __restrict__ feat,
                                                   __nv_bfloat162* __restrict__ aggr,
                                                   const int* __restrict__ rowptr,
                                                   const int* __restrict__ csr) {
    const int lane = threadIdx.x & 31;
    const int grp = lane >> 3;
    const int sub = lane & 7;
    const int node = blockIdx.x * 8 + (threadIdx.x >> 5);
    if (node >= N_NODES) return;
    const int beg = rowptr[node];
    const int end = rowptr[node + 1];
    const __nv_bfloat162* featl = feat + sub * 4;   // lane-invariant base

    __nv_bfloat162 acc[4];
    #pragma unroll
    for (int q = 0; q < 4; q++) acc[q] = __float2bfloat162_rn(0.f);

    for (int j = beg; j < end; j += 8) {
        int e0 = j + grp;
        int e1 = j + 4 + grp;
        if (e0 < end) {
            int s = __ldg(csr + e0);
            uint4 v = *reinterpret_cast<const uint4*>(featl + (size_t)s * 32);
            acc[0] = __hadd2(acc[0], *(__nv_bfloat162*)&v.x);
            acc[1] = __hadd2(acc[1], *(__nv_bfloat162*)&v.y);
            acc[2] = __hadd2(acc[2], *(__nv_bfloat162*)&v.z);
            acc[3] = __hadd2(acc[3], *(__nv_bfloat162*)&v.w);
        }
        if (e1 < end) {
            int s = __ldg(csr + e1);
            uint4 v = *reinterpret_cast<const uint4*>(featl + (size_t)s * 32);
            acc[0] = __hadd2(acc[0], *(__nv_bfloat162*)&v.x);
            acc[1] = __hadd2(acc[1], *(__nv_bfloat162*)&v.y);
            acc[2] = __hadd2(acc[2], *(__nv_bfloat162*)&v.z);
            acc[3] = __hadd2(acc[3], *(__nv_bfloat162*)&v.w);
        }
    }

    // cross-group reduce in f32 (lanes differing in bits 3,4)
    float2 f[4];
    #pragma unroll
    for (int q = 0; q < 4; q++) f[q] = __bfloat1622float2(acc[q]);
    #pragma unroll
    for (int q = 0; q < 4; q++) {
        f[q].x += __shfl_xor_sync(0xffffffffu, f[q].x, 8);
        f[q].y += __shfl_xor_sync(0xffffffffu, f[q].y, 8);
        f[q].x += __shfl_xor_sync(0xffffffffu, f[q].x, 16);
        f[q].y += __shfl_xor_sync(0xffffffffu, f[q].y, 16);
    }
    if (grp == 0) {
        __align__(16) __nv_bfloat162 ob[4];
        #pragma unroll
        for (int q = 0; q < 4; q++) ob[q] = __float22bfloat162_rn(f[q]);
        *reinterpret_cast<uint4*>(aggr + (size_t)node * 32 + sub * 4) =
            *reinterpret_cast<uint4*>(ob);
    }
}

// ---------------- tensor-core GEMM: act([A1|A2] @ (Whi+Wlo) + b) ---------------------
// Block: 64 rows x 64 cols, 128 threads (4 warps, 16 rows each). K = 128 (8 k-steps),
// mma.sync.m16n8k16 bf16, weights hi+lo split. 48KB static smem (best measured shape).
// mode 0: write relu(out). mode 1: fused collapsed layer-3 reduction + last-block
//         final writeout.
__global__ void __launch_bounds__(128) mma_gemm_kernel(
    const __nv_bfloat162* __restrict__ A1, const __nv_bfloat162* __restrict__ A2,
    const __nv_bfloat16* __restrict__ Whi, const __nv_bfloat16* __restrict__ Wlo,
    const float* __restrict__ bias, __nv_bfloat162* __restrict__ out,
    const int* __restrict__ outdeg, const float* __restrict__ wrel3,
    const float* __restrict__ wroot3, double* __restrict__ red,
    unsigned int* __restrict__ cnt, const float* __restrict__ b3,
    float* __restrict__ final_out, int mode) {
    __shared__ __align__(16) __nv_bfloat16 Ash[64 * 128];        // 16KB
    __shared__ __align__(16) __nv_bfloat16 Wsh[2][128 * 64];     // 32KB (total = 48KB)

    const int tid = threadIdx.x;
    const int lane = tid & 31;
    const int warp = tid >> 5;
    const int row_base = blockIdx.x * 64;

    // load A tile: 64 rows x 128 k (A1 k0-63 chunks0-7, A2 k64-127 chunks8-15)
    {
        int r = tid & 63;
        int half = tid >> 6;
        int grow = row_base + r;
        if (grow >= N_NODES) grow = N_NODES - 1;
        const uint4* src = reinterpret_cast<const uint4*>(
            (half ? A2 : A1) + (size_t)grow * 32);
        #pragma unroll
        for (int q = 0; q < 8; q++) {
            uint4 v = src[q];
            int chunk = half * 8 + q;
            int sw = (chunk & 8) | ((chunk ^ r) & 7);
            *reinterpret_cast<uint4*>(Ash + r * 128 + sw * 8) = v;
        }
    }
    // load W hi/lo: 2 x 128 rows x 8 chunks
    {
        #pragma unroll
        for (int q = 0; q < 16; q++) {
            int lin = q * 128 + tid;             // 0..2047
            int hl = lin >> 10;
            int rem = lin & 1023;
            int r = rem >> 3;
            int c = rem & 7;
            uint4 v = reinterpret_cast<const uint4*>((hl ? Wlo : Whi) + r * 64)[c];
            int sw = c ^ (r & 7);
            *reinterpret_cast<uint4*>(Wsh[hl] + r * 64 + sw * 8) = v;
        }
    }
    __syncthreads();

    float d[8][4];
    #pragma unroll
    for (int t = 0; t < 8; t++)
        #pragma unroll
        for (int q = 0; q < 4; q++) d[t][q] = 0.f;

    const int wrow = warp * 16;

    #pragma unroll
    for (int ks = 0; ks < 8; ks++) {
        uint32_t a0, a1, a2, a3;
        {
            int ar = wrow + (lane & 15);
            int ac = ks * 2 + (lane >> 4);
            int sw = (ac & 8) | ((ac ^ ar) & 7);
            uint32_t addr = su32(Ash + ar * 128 + sw * 8);
            asm volatile("ldmatrix.sync.aligned.m8n8.x4.shared.b16 {%0,%1,%2,%3}, [%4];"
                         : "=r"(a0), "=r"(a1), "=r"(a2), "=r"(a3) : "r"(addr));
        }
        #pragma unroll
        for (int hl = 0; hl < 2; hl++) {
            #pragma unroll
            for (int nt2 = 0; nt2 < 4; nt2++) {
                int krow = ks * 16 + (lane & 15);
                int c = nt2 * 2 + (lane >> 4);
                int sw = c ^ (krow & 7);
                uint32_t addr = su32(Wsh[hl] + krow * 64 + sw * 8);
                uint32_t b0, b1, b2, b3r;
                asm volatile("ldmatrix.sync.aligned.m8n8.x4.trans.shared.b16 {%0,%1,%2,%3}, [%4];"
                             : "=r"(b0), "=r"(b1), "=r"(b2), "=r"(b3r) : "r"(addr));
                asm volatile("mma.sync.aligned.m16n8k16.row.col.f32.bf16.bf16.f32 "
                             "{%0,%1,%2,%3},{%4,%5,%6,%7},{%8,%9},{%0,%1,%2,%3};"
                             : "+f"(d[nt2 * 2][0]), "+f"(d[nt2 * 2][1]),
                               "+f"(d[nt2 * 2][2]), "+f"(d[nt2 * 2][3])
                             : "r"(a0), "r"(a1), "r"(a2), "r"(a3), "r"(b0), "r"(b1));
                asm volatile("mma.sync.aligned.m16n8k16.row.col.f32.bf16.bf16.f32 "
                             "{%0,%1,%2,%3},{%4,%5,%6,%7},{%8,%9},{%0,%1,%2,%3};"
                             : "+f"(d[nt2 * 2 + 1][0]), "+f"(d[nt2 * 2 + 1][1]),
                               "+f"(d[nt2 * 2 + 1][2]), "+f"(d[nt2 * 2 + 1][3])
                             : "r"(a0), "r"(a1), "r"(a2), "r"(a3), "r"(b2), "r"(b3r));
            }
        }
    }

    const int g = lane >> 2;
    const int tg = lane & 3;
    const int row0 = row_base + wrow + g;
    const int row1 = row0 + 8;

    if (mode == 0) {
        #pragma unroll
        for (int t = 0; t < 8; t++) {
            int col = 8 * t + 2 * tg;
            float2 bv = *reinterpret_cast<const float2*>(bias + col);
            float o0 = fmaxf(d[t][0] + bv.x, 0.f), o1 = fmaxf(d[t][1] + bv.y, 0.f);
            float o2 = fmaxf(d[t][2] + bv.x, 0.f), o3 = fmaxf(d[t][3] + bv.y, 0.f);
            if (row0 < N_NODES)
                out[(size_t)row0 * 32 + (col >> 1)] = __float22bfloat162_rn(make_float2(o0, o1));
            if (row1 < N_NODES)
                out[(size_t)row1 * 32 + (col >> 1)] = __float22bfloat162_rn(make_float2(o2, o3));
        }
    } else {
        // fused collapsed layer-3: sum_i outdeg[i]*(h2_i . wrel3) + (h2_i . wroot3)
        float r0rel = 0.f, r0root = 0.f, r1rel = 0.f, r1root = 0.f;
        #pragma unroll
        for (int t = 0; t < 8; t++) {
            int col = 8 * t + 2 * tg;
            float2 bv = *reinterpret_cast<const float2*>(bias + col);
            float o0 = fmaxf(d[t][0] + bv.x, 0.f), o1 = fmaxf(d[t][1] + bv.y, 0.f);
            float o2 = fmaxf(d[t][2] + bv.x, 0.f), o3 = fmaxf(d[t][3] + bv.y, 0.f);
            float2 wr = *reinterpret_cast<const float2*>(wrel3 + col);
            float2 wo = *reinterpret_cast<const float2*>(wroot3 + col);
            r0rel  += o0 * wr.x + o1 * wr.y;
            r0root += o0 * wo.x + o1 * wo.y;
            r1rel  += o2 * wr.x + o3 * wr.y;
            r1root += o2 * wo.x + o3 * wo.y;
        }
        #pragma unroll
        for (int off = 1; off <= 2; off <<= 1) {
            r0rel  += __shfl_xor_sync(0xffffffffu, r0rel,  off);
            r0root += __shfl_xor_sync(0xffffffffu, r0root, off);
            r1rel  += __shfl_xor_sync(0xffffffffu, r1rel,  off);
            r1root += __shfl_xor_sync(0xffffffffu, r1root, off);
        }
        float val = 0.f;
        if (tg == 0) {
            if (row0 < N_NODES) val += (float)__ldg(outdeg + row0) * r0rel + r0root;
            if (row1 < N_NODES) val += (float)__ldg(outdeg + row1) * r1rel + r1root;
        }
        val += __shfl_xor_sync(0xffffffffu, val, 4);
        val += __shfl_xor_sync(0xffffffffu, val, 8);
        val += __shfl_xor_sync(0xffffffffu, val, 16);
        if (lane == 0) atomicAdd(red, (double)val);

        // last-block final writeout
        __syncthreads();
        if (tid == 0) {
            __threadfence();
            unsigned int old = atomicInc(cnt, 0xffffffffu);
            if (old == (unsigned int)(gridDim.x - 1)) {
                double r = atomicAdd(red, 0.0);   // all contributions visible
                final_out[0] = (float)(r / (double)N_NODES + (double)b3[0]);
            }
        }
    }
}

// ---------------- launch ----------------
extern "C" void kernel_launch(void* const* d_in, const int* in_sizes, int n_in,
                              void* d_out, int out_size) {
    const float* x      = (const float*)d_in[0];
    const void*  ei     = d_in[1];
    const float* wrel1  = (const float*)d_in[2];
    const float* brel1  = (const float*)d_in[3];
    const float* wroot1 = (const float*)d_in[4];
    const float* wrel2  = (const float*)d_in[5];
    const float* brel2  = (const float*)d_in[6];
    const float* wroot2 = (const float*)d_in[7];
    const float* wrel3  = (const float*)d_in[8];
    const float* brel3  = (const float*)d_in[9];
    const float* wroot3 = (const float*)d_in[10];
    float* out = (float*)d_out;

    __nv_bfloat162 *xbf, *aggr, *h1;
    __nv_bfloat16 *whi, *wlo;
    int *csr, *indeg, *outdeg, *rowtmp, *rowptr, *cursor, *bsum, *is64;
    double* red;
    unsigned int* cnt;
    cudaGetSymbolAddress((void**)&xbf,    g_xbf);
    cudaGetSymbolAddress((void**)&aggr,   g_aggr);
    cudaGetSymbolAddress((void**)&h1,     g_h1);
    cudaGetSymbolAddress((void**)&whi,    g_whi);
    cudaGetSymbolAddress((void**)&wlo,    g_wlo);
    cudaGetSymbolAddress((void**)&csr,    g_csr);
    cudaGetSymbolAddress((void**)&indeg,  g_indeg);
    cudaGetSymbolAddress((void**)&outdeg, g_outdeg);
    cudaGetSymbolAddress((void**)&rowtmp, g_rowtmp);
    cudaGetSymbolAddress((void**)&rowptr, g_rowptr);
    cudaGetSymbolAddress((void**)&cursor, g_cursor);
    cudaGetSymbolAddress((void**)&bsum,   g_bsum);
    cudaGetSymbolAddress((void**)&red,    g_red);
    cudaGetSymbolAddress((void**)&cnt,    g_cnt);
    cudaGetSymbolAddress((void**)&is64,   g_is64);

    const int eblk = (N_EDGES + 255) / 256;     // 6250
    const int nblk = (N_NODES + 255) / 256;     // 391
    const int ablk = (N_NODES + 7) / 8;         // 12500

    // prep + CSR build (R10 structure — measured fastest)
    detect_zero_kernel<<<nblk, 256>>>((const unsigned int*)ei, is64, indeg, outdeg, red, cnt);
    histconv_kernel<<<eblk, 256>>>(ei, x, xbf, indeg, outdeg, is64,
                                   wrel1, wroot1, wrel2, wroot2, whi, wlo);
    scan1_kernel<<<SCAN_BLOCKS, 512>>>(indeg, rowtmp, bsum);
    scan23_kernel<<<nblk, 256>>>(rowtmp, bsum, indeg, rowptr, cursor);
    fill_kernel<<<eblk, 256>>>(ei, cursor, csr, is64);

    // layer 1
    aggr_kernel<<<ablk, 256>>>(xbf, aggr, rowptr, csr);
    mma_gemm_kernel<<<GBLK, 128>>>(aggr, xbf, whi, wlo, brel1, h1,
                                   nullptr, nullptr, nullptr, nullptr, nullptr,
                                   nullptr, nullptr, 0);
    // layer 2 (+ fused collapsed layer-3 reduction + last-block final writeout)
    aggr_kernel<<<ablk, 256>>>(h1, aggr, rowptr, csr);
    mma_gemm_kernel<<<GBLK, 128>>>(aggr, h1, whi + 8192, wlo + 8192, brel2, nullptr,
                                   outdeg, wrel3, wroot3, red, cnt, brel3, out, 1);
}

// round 14
// speedup vs baseline: 1.4457x; 1.0262x over previous
#include <cuda_runtime.h>
#include <cuda_bf16.h>
#include <cstdint>

#define N_NODES 100000
#define N_EDGES 1600000
#define NF 64
#define SCAN_BLOCKS 196           // ceil(100000/512)
#define GBLK 1563                 // ceil(100000/64)

// ---------------- scratch (static __device__ — no allocations allowed) ----------------
__device__ __nv_bfloat162 g_xbf [(size_t)N_NODES * 32];
__device__ __nv_bfloat162 g_aggr[(size_t)N_NODES * 32];
__device__ __nv_bfloat162 g_h1  [(size_t)N_NODES * 32];
__device__ __nv_bfloat16  g_whi [2 * 128 * 64];
__device__ __nv_bfloat16  g_wlo [2 * 128 * 64];
__device__ int   g_csr[N_EDGES];
__device__ int   g_indeg[N_NODES];
__device__ int   g_outdeg[N_NODES];
__device__ int   g_rowtmp[N_NODES];
__device__ int   g_rowptr[N_NODES + 1];
__device__ int   g_cursor[N_NODES];
__device__ int   g_bsum[256];
__device__ double g_red[1];
__device__ unsigned int g_cnt[1];
__device__ int   g_is64[1];

static __device__ __forceinline__ uint32_t su32(const void* p) {
    return (uint32_t)__cvta_generic_to_shared(p);
}

// ---------------- detect dtype (block 0) + zero indeg/outdeg/red/cnt -----------------
__global__ void __launch_bounds__(256) detect_zero_kernel(
    const unsigned int* __restrict__ w, int* __restrict__ flag,
    int* __restrict__ indeg, int* __restrict__ outdeg, double* __restrict__ red,
    unsigned int* __restrict__ cnt) {
    int i = blockIdx.x * 256 + threadIdx.x;
    if (i < N_NODES) { indeg[i] = 0; outdeg[i] = 0; }
    if (i == 0) { red[0] = 0.0; cnt[0] = 0u; }
    if (blockIdx.x == 0 && threadIdx.x < 64) {
        // int64 layout => every odd 32-bit word is the (zero) high half of a small id.
        unsigned int idx = 2u * (unsigned int)(threadIdx.x * 24999 + 13) + 1u;
        unsigned int v = w[idx];
        #pragma unroll
        for (int off = 16; off; off >>= 1)
            v |= __shfl_xor_sync(0xffffffffu, v, off);
        __shared__ unsigned int s0, s1;
        if (threadIdx.x == 0)  s0 = v;
        if (threadIdx.x == 32) s1 = v;
        __syncthreads();
        if (threadIdx.x == 0) *flag = ((s0 | s1) == 0u) ? 1 : 0;
    }
}

// ---------------- fused: degree hist + x->bf16 + weight hi/lo split ----------------
__global__ void __launch_bounds__(256) histconv_kernel(
    const void* __restrict__ ei, const float* __restrict__ x,
    __nv_bfloat162* __restrict__ xbf, int* __restrict__ indeg,
    int* __restrict__ outdeg, const int* __restrict__ flag,
    const float* __restrict__ wrel1, const float* __restrict__ wroot1,
    const float* __restrict__ wrel2, const float* __restrict__ wroot2,
    __nv_bfloat16* __restrict__ whi, __nv_bfloat16* __restrict__ wlo) {
    int idx = blockIdx.x * 256 + threadIdx.x;
    if (idx < (N_NODES * NF) / 8) {          // one uint4 of bf16 out per thread
        const float4* xs = (const float4*)x;
        float4 v0 = xs[2 * idx], v1 = xs[2 * idx + 1];
        __align__(16) __nv_bfloat162 o[4];
        o[0] = __float22bfloat162_rn(make_float2(v0.x, v0.y));
        o[1] = __float22bfloat162_rn(make_float2(v0.z, v0.w));
        o[2] = __float22bfloat162_rn(make_float2(v1.x, v1.y));
        o[3] = __float22bfloat162_rn(make_float2(v1.z, v1.w));
        reinterpret_cast<uint4*>(xbf)[idx] = *reinterpret_cast<uint4*>(o);
    }
    if (idx < 2 * 128 * 64) {                // weight hi/lo split
        int layer = idx >> 13;
        int rem = idx & 8191;
        int k = rem >> 6;
        int nn = rem & 63;
        const float* src = layer ? (k < 64 ? wrel2 : wroot2) : (k < 64 ? wrel1 : wroot1);
        float w = src[(k & 63) * 64 + nn];
        __nv_bfloat16 hi = __float2bfloat16(w);
        __nv_bfloat16 lo = __float2bfloat16(w - __bfloat162float(hi));
        whi[idx] = hi;
        wlo[idx] = lo;
    }
    if (idx < N_EDGES) {
        int s, d;
        if (*flag) {
            const long long* p = (const long long*)ei;
            s = (int)p[idx];
            d = (int)p[N_EDGES + idx];
        } else {
            const int* p = (const int*)ei;
            s = p[idx];
            d = p[N_EDGES + idx];
        }
        atomicAdd(indeg + d, 1);
        atomicAdd(outdeg + s, 1);
    }
}

// ---------------- scan: block-local inclusive scan (shuffle) ----------------
__global__ void scan1_kernel(const int* __restrict__ indeg, int* __restrict__ rowtmp,
                             int* __restrict__ bsum) {
    __shared__ int warpsum[16];
    int tid = threadIdx.x;
    int i = blockIdx.x * 512 + tid;
    int v = (i < N_NODES) ? indeg[i] : 0;
    int lane = tid & 31, w = tid >> 5;
    #pragma unroll
    for (int off = 1; off < 32; off <<= 1) {
        int t = __shfl_up_sync(0xffffffffu, v, off);
        if (lane >= off) v += t;
    }
    if (lane == 31) warpsum[w] = v;
    __syncthreads();
    if (w == 0) {
        int s = (lane < 16) ? warpsum[lane] : 0;
        #pragma unroll
        for (int off = 1; off < 16; off <<= 1) {
            int t = __shfl_up_sync(0xffffffffu, s, off);
            if (lane >= off) s += t;
        }
        if (lane < 16) warpsum[lane] = s;
    }
    __syncthreads();
    if (w > 0) v += warpsum[w - 1];
    if (i < N_NODES) rowtmp[i] = v;
    if (tid == 511) bsum[blockIdx.x] = v;
}

// scan of block sums (redundant per block, shuffle) + apply -> rowptr, cursor
__global__ void scan23_kernel(const int* __restrict__ rowtmp, const int* __restrict__ bsum,
                              const int* __restrict__ indeg, int* __restrict__ rowptr,
                              int* __restrict__ cursor) {
    __shared__ int bs[256];
    __shared__ int wsum[8];
    int tid = threadIdx.x;
    int lane = tid & 31, w = tid >> 5;
    int v = (tid < SCAN_BLOCKS) ? bsum[tid] : 0;
    #pragma unroll
    for (int off = 1; off < 32; off <<= 1) {
        int t = __shfl_up_sync(0xffffffffu, v, off);
        if (lane >= off) v += t;
    }
    if (lane == 31) wsum[w] = v;
    __syncthreads();
    if (w == 0 && lane < 8) {
        int s = wsum[lane];
        #pragma unroll
        for (int off = 1; off < 8; off <<= 1) {
            int t = __shfl_up_sync(0xffu, s, off);
            if (lane >= off) s += t;
        }
        wsum[lane] = s;
    }
    __syncthreads();
    if (w > 0) v += wsum[w - 1];
    bs[tid] = v;                 // inclusive scan of block sums
    __syncthreads();

    int i = blockIdx.x * 256 + tid;
    if (i >= N_NODES) return;
    int b = i >> 9;
    int add = (b > 0) ? bs[b - 1] : 0;
    int inc = rowtmp[i] + add;
    rowptr[i + 1] = inc;
    cursor[i] = inc - indeg[i];
    if (i == 0) rowptr[0] = 0;
}

__global__ void fill_kernel(const void* __restrict__ ei, int* __restrict__ cursor,
                            int* __restrict__ csr, const int* __restrict__ flag) {
    int e = blockIdx.x * blockDim.x + threadIdx.x;
    if (e >= N_EDGES) return;
    int s, d;
    if (*flag) {
        const long long* p = (const long long*)ei;
        s = (int)p[e];
        d = (int)p[N_EDGES + e];
    } else {
        const int* p = (const int*)ei;
        s = p[e];
        d = p[N_EDGES + e];
    }
    int pos = atomicAdd(cursor + d, 1);
    csr[pos] = s;
}

// ---------------- aggregation: aggr[i] = sum_{j in N(i)} feat[j] (bf16) --------------
// one warp per node; 8 edges in flight; each 8-lane group loads a 128B row (LDG.128).
// bf16x2 accumulation (HADD2); cross-group reduce also in packed bf16x2 (shfl the raw
// u32 accumulator + HADD2) — no f32 unpack/repack in the epilogue.
__global__ void __launch_bounds__(256) aggr_kernel(const __nv_bfloat162* __restrict__ feat,
                                                   __nv_bfloat162* __restrict__ aggr,
                                                   const int* __restrict__ rowptr,
                                                   const int* __restrict__ csr) {
    const int lane = threadIdx.x & 31;
    const int grp = lane >> 3;
    const int sub = lane & 7;
    const int node = blockIdx.x * 8 + (threadIdx.x >> 5);
    if (node >= N_NODES) return;
    const int beg = rowptr[node];
    const int end = rowptr[node + 1];
    const __nv_bfloat162* featl = feat + sub * 4;   // lane-invariant base

    __nv_bfloat162 acc[4];
    #pragma unroll
    for (int q = 0; q < 4; q++) acc[q] = __float2bfloat162_rn(0.f);

    for (int j = beg; j < end; j += 8) {
        int e0 = j + grp;
        int e1 = j + 4 + grp;
        if (e0 < end) {
            int s = __ldg(csr + e0);
            uint4 v = *reinterpret_cast<const uint4*>(featl + (size_t)s * 32);
            acc[0] = __hadd2(acc[0], *(__nv_bfloat162*)&v.x);
            acc[1] = __hadd2(acc[1], *(__nv_bfloat162*)&v.y);
            acc[2] = __hadd2(acc[2], *(__nv_bfloat162*)&v.z);
            acc[3] = __hadd2(acc[3], *(__nv_bfloat162*)&v.w);
        }
        if (e1 < end) {
            int s = __ldg(csr + e1);
            uint4 v = *reinterpret_cast<const uint4*>(featl + (size_t)s * 32);
            acc[0] = __hadd2(acc[0], *(__nv_bfloat162*)&v.x);
            acc[1] = __hadd2(acc[1], *(__nv_bfloat162*)&v.y);
            acc[2] = __hadd2(acc[2], *(__nv_bfloat162*)&v.z);
            acc[3] = __hadd2(acc[3], *(__nv_bfloat162*)&v.w);
        }
    }

    // cross-group reduce in packed bf16x2 (lanes differing in bits 3,4)
    #pragma unroll
    for (int q = 0; q < 4; q++) {
        unsigned int u = *reinterpret_cast<unsigned int*>(&acc[q]);
        unsigned int o = __shfl_xor_sync(0xffffffffu, u, 8);
        acc[q] = __hadd2(acc[q], *reinterpret_cast<__nv_bfloat162*>(&o));
        u = *reinterpret_cast<unsigned int*>(&acc[q]);
        o = __shfl_xor_sync(0xffffffffu, u, 16);
        acc[q] = __hadd2(acc[q], *reinterpret_cast<__nv_bfloat162*>(&o));
    }
    if (grp == 0) {
        *reinterpret_cast<uint4*>(aggr + (size_t)node * 32 + sub * 4) =
            *reinterpret_cast<uint4*>(acc);
    }
}

// ---------------- tensor-core GEMM: act([A1|A2] @ (Whi+Wlo) + b) ---------------------
// Block: 64 rows x 64 cols, 128 threads (4 warps, 16 rows each). K = 128 (8 k-steps),
// mma.sync.m16n8k16 bf16, weights hi+lo split. 48KB static smem (best measured shape).
// mode 0: write relu(out). mode 1: fused collapsed layer-3 reduction + last-block
//         final writeout.
__global__ void __launch_bounds__(128) mma_gemm_kernel(
    const __nv_bfloat162* __restrict__ A1, const __nv_bfloat162* __restrict__ A2,
    const __nv_bfloat16* __restrict__ Whi, const __nv_bfloat16* __restrict__ Wlo,
    const float* __restrict__ bias, __nv_bfloat162* __restrict__ out,
    const int* __restrict__ outdeg, const float* __restrict__ wrel3,
    const float* __restrict__ wroot3, double* __restrict__ red,
    unsigned int* __restrict__ cnt, const float* __restrict__ b3,
    float* __restrict__ final_out, int mode) {
    __shared__ __align__(16) __nv_bfloat16 Ash[64 * 128];        // 16KB
    __shared__ __align__(16) __nv_bfloat16 Wsh[2][128 * 64];     // 32KB (total = 48KB)

    const int tid = threadIdx.x;
    const int lane = tid & 31;
    const int warp = tid >> 5;
    const int row_base = blockIdx.x * 64;

    // load A tile: 64 rows x 128 k (A1 k0-63 chunks0-7, A2 k64-127 chunks8-15)
    {
        int r = tid & 63;
        int half = tid >> 6;
        int grow = row_base + r;
        if (grow >= N_NODES) grow = N_NODES - 1;
        const uint4* src = reinterpret_cast<const uint4*>(
            (half ? A2 : A1) + (size_t)grow * 32);
        #pragma unroll
        for (int q = 0; q < 8; q++) {
            uint4 v = src[q];
            int chunk = half * 8 + q;
            int sw = (chunk & 8) | ((chunk ^ r) & 7);
            *reinterpret_cast<uint4*>(Ash + r * 128 + sw * 8) = v;
        }
    }
    // load W hi/lo: 2 x 128 rows x 8 chunks
    {
        #pragma unroll
        for (int q = 0; q < 16; q++) {
            int lin = q * 128 + tid;             // 0..2047
            int hl = lin >> 10;
            int rem = lin & 1023;
            int r = rem >> 3;
            int c = rem & 7;
            uint4 v = reinterpret_cast<const uint4*>((hl ? Wlo : Whi) + r * 64)[c];
            int sw = c ^ (r & 7);
            *reinterpret_cast<uint4*>(Wsh[hl] + r * 64 + sw * 8) = v;
        }
    }
    __syncthreads();

    float d[8][4];
    #pragma unroll
    for (int t = 0; t < 8; t++)
        #pragma unroll
        for (int q = 0; q < 4; q++) d[t][q] = 0.f;

    const int wrow = warp * 16;

    #pragma unroll
    for (int ks = 0; ks < 8; ks++) {
        uint32_t a0, a1, a2, a3;
        {
            int ar = wrow + (lane & 15);
            int ac = ks * 2 + (lane >> 4);
            int sw = (ac & 8) | ((ac ^ ar) & 7);
            uint32_t addr = su32(Ash + ar * 128 + sw * 8);
            asm volatile("ldmatrix.sync.aligned.m8n8.x4.shared.b16 {%0,%1,%2,%3}, [%4];"
                         : "=r"(a0), "=r"(a1), "=r"(a2), "=r"(a3) : "r"(addr));
        }
        #pragma unroll
        for (int hl = 0; hl < 2; hl++) {
            #pragma unroll
            for (int nt2 = 0; nt2 < 4; nt2++) {
                int krow = ks * 16 + (lane & 15);
                int c = nt2 * 2 + (lane >> 4);
                int sw = c ^ (krow & 7);
                uint32_t addr = su32(Wsh[hl] + krow * 64 + sw * 8);
                uint32_t b0, b1, b2, b3r;
                asm volatile("ldmatrix.sync.aligned.m8n8.x4.trans.shared.b16 {%0,%1,%2,%3}, [%4];"
                             : "=r"(b0), "=r"(b1), "=r"(b2), "=r"(b3r) : "r"(addr));
                asm volatile("mma.sync.aligned.m16n8k16.row.col.f32.bf16.bf16.f32 "
                             "{%0,%1,%2,%3},{%4,%5,%6,%7},{%8,%9},{%0,%1,%2,%3};"
                             : "+f"(d[nt2 * 2][0]), "+f"(d[nt2 * 2][1]),
                               "+f"(d[nt2 * 2][2]), "+f"(d[nt2 * 2][3])
                             : "r"(a0), "r"(a1), "r"(a2), "r"(a3), "r"(b0), "r"(b1));
                asm volatile("mma.sync.aligned.m16n8k16.row.col.f32.bf16.bf16.f32 "
                             "{%0,%1,%2,%3},{%4,%5,%6,%7},{%8,%9},{%0,%1,%2,%3};"
                             : "+f"(d[nt2 * 2 + 1][0]), "+f"(d[nt2 * 2 + 1][1]),
                               "+f"(d[nt2 * 2 + 1][2]), "+f"(d[nt2 * 2 + 1][3])
                             : "r"(a0), "r"(a1), "r"(a2), "r"(a3), "r"(b2), "r"(b3r));
            }
        }
    }

    const int g = lane >> 2;
    const int tg = lane & 3;
    const int row0 = row_base + wrow + g;
    const int row1 = row0 + 8;

    if (mode == 0) {
        #pragma unroll
        for (int t = 0; t < 8; t++) {
            int col = 8 * t + 2 * tg;
            float2 bv = *reinterpret_cast<const float2*>(bias + col);
            float o0 = fmaxf(d[t][0] + bv.x, 0.f), o1 = fmaxf(d[t][1] + bv.y, 0.f);
            float o2 = fmaxf(d[t][2] + bv.x, 0.f), o3 = fmaxf(d[t][3] + bv.y, 0.f);
            if (row0 < N_NODES)
                out[(size_t)row0 * 32 + (col >> 1)] = __float22bfloat162_rn(make_float2(o0, o1));
            if (row1 < N_NODES)
                out[(size_t)row1 * 32 + (col >> 1)] = __float22bfloat162_rn(make_float2(o2, o3));
        }
    } else {
        // fused collapsed layer-3: sum_i outdeg[i]*(h2_i . wrel3) + (h2_i . wroot3)
        float r0rel = 0.f, r0root = 0.f, r1rel = 0.f, r1root = 0.f;
        #pragma unroll
        for (int t = 0; t < 8; t++) {
            int col = 8 * t + 2 * tg;
            float2 bv = *reinterpret_cast<const float2*>(bias + col);
            float o0 = fmaxf(d[t][0] + bv.x, 0.f), o1 = fmaxf(d[t][1] + bv.y, 0.f);
            float o2 = fmaxf(d[t][2] + bv.x, 0.f), o3 = fmaxf(d[t][3] + bv.y, 0.f);
            float2 wr = *reinterpret_cast<const float2*>(wrel3 + col);
            float2 wo = *reinterpret_cast<const float2*>(wroot3 + col);
            r0rel  += o0 * wr.x + o1 * wr.y;
            r0root += o0 * wo.x + o1 * wo.y;
            r1rel  += o2 * wr.x + o3 * wr.y;
            r1root += o2 * wo.x + o3 * wo.y;
        }
        #pragma unroll
        for (int off = 1; off <= 2; off <<= 1) {
            r0rel  += __shfl_xor_sync(0xffffffffu, r0rel,  off);
            r0root += __shfl_xor_sync(0xffffffffu, r0root, off);
            r1rel  += __shfl_xor_sync(0xffffffffu, r1rel,  off);
            r1root += __shfl_xor_sync(0xffffffffu, r1root, off);
        }
        float val = 0.f;
        if (tg == 0) {
            if (row0 < N_NODES) val += (float)__ldg(outdeg + row0) * r0rel + r0root;
            if (row1 < N_NODES) val += (float)__ldg(outdeg + row1) * r1rel + r1root;
        }
        val += __shfl_xor_sync(0xffffffffu, val, 4);
        val += __shfl_xor_sync(0xffffffffu, val, 8);
        val += __shfl_xor_sync(0xffffffffu, val, 16);
        if (lane == 0) atomicAdd(red, (double)val);

        // last-block final writeout
        __syncthreads();
        if (tid == 0) {
            __threadfence();
            unsigned int old = atomicInc(cnt, 0xffffffffu);
            if (old == (unsigned int)(gridDim.x - 1)) {
                double r = atomicAdd(red, 0.0);   // all contributions visible
                final_out[0] = (float)(r / (double)N_NODES + (double)b3[0]);
            }
        }
    }
}

// ---------------- launch ----------------
extern "C" void kernel_launch(void* const* d_in, const int* in_sizes, int n_in,
                              void* d_out, int out_size) {
    const float* x      = (const float*)d_in[0];
    const void*  ei     = d_in[1];
    const float* wrel1  = (const float*)d_in[2];
    const float* brel1  = (const float*)d_in[3];
    const float* wroot1 = (const float*)d_in[4];
    const float* wrel2  = (const float*)d_in[5];
    const float* brel2  = (const float*)d_in[6];
    const float* wroot2 = (const float*)d_in[7];
    const float* wrel3  = (const float*)d_in[8];
    const float* brel3  = (const float*)d_in[9];
    const float* wroot3 = (const float*)d_in[10];
    float* out = (float*)d_out;

    __nv_bfloat162 *xbf, *aggr, *h1;
    __nv_bfloat16 *whi, *wlo;
    int *csr, *indeg, *outdeg, *rowtmp, *rowptr, *cursor, *bsum, *is64;
    double* red;
    unsigned int* cnt;
    cudaGetSymbolAddress((void**)&xbf,    g_xbf);
    cudaGetSymbolAddress((void**)&aggr,   g_aggr);
    cudaGetSymbolAddress((void**)&h1,     g_h1);
    cudaGetSymbolAddress((void**)&whi,    g_whi);
    cudaGetSymbolAddress((void**)&wlo,    g_wlo);
    cudaGetSymbolAddress((void**)&csr,    g_csr);
    cudaGetSymbolAddress((void**)&indeg,  g_indeg);
    cudaGetSymbolAddress((void**)&outdeg, g_outdeg);
    cudaGetSymbolAddress((void**)&rowtmp, g_rowtmp);
    cudaGetSymbolAddress((void**)&rowptr, g_rowptr);
    cudaGetSymbolAddress((void**)&cursor, g_cursor);
    cudaGetSymbolAddress((void**)&bsum,   g_bsum);
    cudaGetSymbolAddress((void**)&red,    g_red);
    cudaGetSymbolAddress((void**)&cnt,    g_cnt);
    cudaGetSymbolAddress((void**)&is64,   g_is64);

    const int eblk = (N_EDGES + 255) / 256;     // 6250
    const int nblk = (N_NODES + 255) / 256;     // 391
    const int ablk = (N_NODES + 7) / 8;         // 12500

    // prep + CSR build (R10 structure — measured fastest)
    detect_zero_kernel<<<nblk, 256>>>((const unsigned int*)ei, is64, indeg, outdeg, red, cnt);
    histconv_kernel<<<eblk, 256>>>(ei, x, xbf, indeg, outdeg, is64,
                                   wrel1, wroot1, wrel2, wroot2, whi, wlo);
    scan1_kernel<<<SCAN_BLOCKS, 512>>>(indeg, rowtmp, bsum);
    scan23_kernel<<<nblk, 256>>>(rowtmp, bsum, indeg, rowptr, cursor);
    fill_kernel<<<eblk, 256>>>(ei, cursor, csr, is64);

    // layer 1
    aggr_kernel<<<ablk, 256>>>(xbf, aggr, rowptr, csr);
    mma_gemm_kernel<<<GBLK, 128>>>(aggr, xbf, whi, wlo, brel1, h1,
                                   nullptr, nullptr, nullptr, nullptr, nullptr,
                                   nullptr, nullptr, 0);
    // layer 2 (+ fused collapsed layer-3 reduction + last-block final writeout)
    aggr_kernel<<<ablk, 256>>>(h1, aggr, rowptr, csr);
    mma_gemm_kernel<<<GBLK, 128>>>(aggr, h1, whi + 8192, wlo + 8192, brel2, nullptr,
                                   outdeg, wrel3, wroot3, red, cnt, brel3, out, 1);
}

// round 15
// speedup vs baseline: 1.4676x; 1.0152x over previous
#include <cuda_runtime.h>
#include <cuda_bf16.h>
#include <cstdint>

#define N_NODES 100000
#define N_EDGES 1600000
#define NF 64
#define SCAN_BLOCKS 196           // ceil(100000/512)
#define GBLK 1563                 // ceil(100000/64)

// ---------------- scratch (static __device__ — no allocations allowed) ----------------
__device__ __nv_bfloat162 g_xbf [(size_t)N_NODES * 32];
__device__ __nv_bfloat162 g_aggr[(size_t)N_NODES * 32];
__device__ __nv_bfloat162 g_h1  [(size_t)N_NODES * 32];
__device__ __nv_bfloat16  g_whi [2 * 128 * 64];
__device__ __nv_bfloat16  g_wlo [2 * 128 * 64];
__device__ int   g_csr[N_EDGES];
__device__ int   g_indeg[N_NODES];
__device__ int   g_outdeg[N_NODES];
__device__ int   g_rowtmp[N_NODES];
__device__ int   g_rowptr[N_NODES + 1];
__device__ int   g_cursor[N_NODES];
__device__ int   g_bsum[256];
__device__ double g_red[1];
__device__ unsigned int g_cnt[1];
__device__ int   g_is64[1];

static __device__ __forceinline__ uint32_t su32(const void* p) {
    return (uint32_t)__cvta_generic_to_shared(p);
}

// ---------------- detect dtype (block 0) + zero indeg/outdeg/red/cnt -----------------
__global__ void __launch_bounds__(256) detect_zero_kernel(
    const unsigned int* __restrict__ w, int* __restrict__ flag,
    int* __restrict__ indeg, int* __restrict__ outdeg, double* __restrict__ red,
    unsigned int* __restrict__ cnt) {
    int i = blockIdx.x * 256 + threadIdx.x;
    if (i < N_NODES) { indeg[i] = 0; outdeg[i] = 0; }
    if (i == 0) { red[0] = 0.0; cnt[0] = 0u; }
    if (blockIdx.x == 0 && threadIdx.x < 64) {
        // int64 layout => every odd 32-bit word is the (zero) high half of a small id.
        unsigned int idx = 2u * (unsigned int)(threadIdx.x * 24999 + 13) + 1u;
        unsigned int v = w[idx];
        #pragma unroll
        for (int off = 16; off; off >>= 1)
            v |= __shfl_xor_sync(0xffffffffu, v, off);
        __shared__ unsigned int s0, s1;
        if (threadIdx.x == 0)  s0 = v;
        if (threadIdx.x == 32) s1 = v;
        __syncthreads();
        if (threadIdx.x == 0) *flag = ((s0 | s1) == 0u) ? 1 : 0;
    }
}

// ---------------- fused: degree hist + x->bf16 + weight hi/lo split ----------------
__global__ void __launch_bounds__(256) histconv_kernel(
    const void* __restrict__ ei, const float* __restrict__ x,
    __nv_bfloat162* __restrict__ xbf, int* __restrict__ indeg,
    int* __restrict__ outdeg, const int* __restrict__ flag,
    const float* __restrict__ wrel1, const float* __restrict__ wroot1,
    const float* __restrict__ wrel2, const float* __restrict__ wroot2,
    __nv_bfloat16* __restrict__ whi, __nv_bfloat16* __restrict__ wlo) {
    int idx = blockIdx.x * 256 + threadIdx.x;
    if (idx < (N_NODES * NF) / 8) {          // one uint4 of bf16 out per thread
        const float4* xs = (const float4*)x;
        float4 v0 = xs[2 * idx], v1 = xs[2 * idx + 1];
        __align__(16) __nv_bfloat162 o[4];
        o[0] = __float22bfloat162_rn(make_float2(v0.x, v0.y));
        o[1] = __float22bfloat162_rn(make_float2(v0.z, v0.w));
        o[2] = __float22bfloat162_rn(make_float2(v1.x, v1.y));
        o[3] = __float22bfloat162_rn(make_float2(v1.z, v1.w));
        reinterpret_cast<uint4*>(xbf)[idx] = *reinterpret_cast<uint4*>(o);
    }
    if (idx < 2 * 128 * 64) {                // weight hi/lo split
        int layer = idx >> 13;
        int rem = idx & 8191;
        int k = rem >> 6;
        int nn = rem & 63;
        const float* src = layer ? (k < 64 ? wrel2 : wroot2) : (k < 64 ? wrel1 : wroot1);
        float w = src[(k & 63) * 64 + nn];
        __nv_bfloat16 hi = __float2bfloat16(w);
        __nv_bfloat16 lo = __float2bfloat16(w - __bfloat162float(hi));
        whi[idx] = hi;
        wlo[idx] = lo;
    }
    if (idx < N_EDGES) {
        int s, d;
        if (*flag) {
            const long long* p = (const long long*)ei;
            s = (int)p[idx];
            d = (int)p[N_EDGES + idx];
        } else {
            const int* p = (const int*)ei;
            s = p[idx];
            d = p[N_EDGES + idx];
        }
        atomicAdd(indeg + d, 1);
        atomicAdd(outdeg + s, 1);
    }
}

// ---------------- scan: block-local inclusive scan (shuffle) ----------------
__global__ void scan1_kernel(const int* __restrict__ indeg, int* __restrict__ rowtmp,
                             int* __restrict__ bsum) {
    __shared__ int warpsum[16];
    int tid = threadIdx.x;
    int i = blockIdx.x * 512 + tid;
    int v = (i < N_NODES) ? indeg[i] : 0;
    int lane = tid & 31, w = tid >> 5;
    #pragma unroll
    for (int off = 1; off < 32; off <<= 1) {
        int t = __shfl_up_sync(0xffffffffu, v, off);
        if (lane >= off) v += t;
    }
    if (lane == 31) warpsum[w] = v;
    __syncthreads();
    if (w == 0) {
        int s = (lane < 16) ? warpsum[lane] : 0;
        #pragma unroll
        for (int off = 1; off < 16; off <<= 1) {
            int t = __shfl_up_sync(0xffffffffu, s, off);
            if (lane >= off) s += t;
        }
        if (lane < 16) warpsum[lane] = s;
    }
    __syncthreads();
    if (w > 0) v += warpsum[w - 1];
    if (i < N_NODES) rowtmp[i] = v;
    if (tid == 511) bsum[blockIdx.x] = v;
}

// scan of block sums (redundant per block, shuffle) + apply -> rowptr, cursor
__global__ void scan23_kernel(const int* __restrict__ rowtmp, const int* __restrict__ bsum,
                              const int* __restrict__ indeg, int* __restrict__ rowptr,
                              int* __restrict__ cursor) {
    __shared__ int bs[256];
    __shared__ int wsum[8];
    int tid = threadIdx.x;
    int lane = tid & 31, w = tid >> 5;
    int v = (tid < SCAN_BLOCKS) ? bsum[tid] : 0;
    #pragma unroll
    for (int off = 1; off < 32; off <<= 1) {
        int t = __shfl_up_sync(0xffffffffu, v, off);
        if (lane >= off) v += t;
    }
    if (lane == 31) wsum[w] = v;
    __syncthreads();
    if (w == 0 && lane < 8) {
        int s = wsum[lane];
        #pragma unroll
        for (int off = 1; off < 8; off <<= 1) {
            int t = __shfl_up_sync(0xffu, s, off);
            if (lane >= off) s += t;
        }
        wsum[lane] = s;
    }
    __syncthreads();
    if (w > 0) v += wsum[w - 1];
    bs[tid] = v;                 // inclusive scan of block sums
    __syncthreads();

    int i = blockIdx.x * 256 + tid;
    if (i >= N_NODES) return;
    int b = i >> 9;
    int add = (b > 0) ? bs[b - 1] : 0;
    int inc = rowtmp[i] + add;
    rowptr[i + 1] = inc;
    cursor[i] = inc - indeg[i];
    if (i == 0) rowptr[0] = 0;
}

__global__ void fill_kernel(const void* __restrict__ ei, int* __restrict__ cursor,
                            int* __restrict__ csr, const int* __restrict__ flag) {
    int e = blockIdx.x * blockDim.x + threadIdx.x;
    if (e >= N_EDGES) return;
    int s, d;
    if (*flag) {
        const long long* p = (const long long*)ei;
        s = (int)p[e];
        d = (int)p[N_EDGES + e];
    } else {
        const int* p = (const int*)ei;
        s = p[e];
        d = p[N_EDGES + e];
    }
    int pos = atomicAdd(cursor + d, 1);
    csr[pos] = s;
}

// ---------------- aggregation: aggr[i] = sum_{j in N(i)} feat[j] (bf16) --------------
// one warp per node; 8 edges in flight; each 8-lane group loads a 128B row (LDG.128).
// Main loop covers full 8-edge chunks with NO predication; one predicated tail block.
// bf16x2 accumulation (HADD2); packed bf16x2 cross-group shuffle reduce.
__global__ void __launch_bounds__(256) aggr_kernel(const __nv_bfloat162* __restrict__ feat,
                                                   __nv_bfloat162* __restrict__ aggr,
                                                   const int* __restrict__ rowptr,
                                                   const int* __restrict__ csr) {
    const int lane = threadIdx.x & 31;
    const int grp = lane >> 3;
    const int sub = lane & 7;
    const int node = blockIdx.x * 8 + (threadIdx.x >> 5);
    if (node >= N_NODES) return;
    const int beg = rowptr[node];
    const int end = rowptr[node + 1];
    const __nv_bfloat162* featl = feat + sub * 4;   // lane-invariant base

    __nv_bfloat162 acc[4];
    #pragma unroll
    for (int q = 0; q < 4; q++) acc[q] = __float2bfloat162_rn(0.f);

    const int mfull = beg + ((end - beg) & ~7);     // full 8-edge chunks
    int j = beg;
    for (; j < mfull; j += 8) {
        int s0 = __ldg(csr + j + grp);
        int s1 = __ldg(csr + j + 4 + grp);
        uint4 v0 = *reinterpret_cast<const uint4*>(featl + (size_t)s0 * 32);
        uint4 v1 = *reinterpret_cast<const uint4*>(featl + (size_t)s1 * 32);
        acc[0] = __hadd2(acc[0], *(__nv_bfloat162*)&v0.x);
        acc[1] = __hadd2(acc[1], *(__nv_bfloat162*)&v0.y);
        acc[2] = __hadd2(acc[2], *(__nv_bfloat162*)&v0.z);
        acc[3] = __hadd2(acc[3], *(__nv_bfloat162*)&v0.w);
        acc[0] = __hadd2(acc[0], *(__nv_bfloat162*)&v1.x);
        acc[1] = __hadd2(acc[1], *(__nv_bfloat162*)&v1.y);
        acc[2] = __hadd2(acc[2], *(__nv_bfloat162*)&v1.z);
        acc[3] = __hadd2(acc[3], *(__nv_bfloat162*)&v1.w);
    }
    if (j < end) {                                  // predicated tail (0-7 edges)
        int e0 = j + grp;
        int e1 = j + 4 + grp;
        if (e0 < end) {
            int s = __ldg(csr + e0);
            uint4 v = *reinterpret_cast<const uint4*>(featl + (size_t)s * 32);
            acc[0] = __hadd2(acc[0], *(__nv_bfloat162*)&v.x);
            acc[1] = __hadd2(acc[1], *(__nv_bfloat162*)&v.y);
            acc[2] = __hadd2(acc[2], *(__nv_bfloat162*)&v.z);
            acc[3] = __hadd2(acc[3], *(__nv_bfloat162*)&v.w);
        }
        if (e1 < end) {
            int s = __ldg(csr + e1);
            uint4 v = *reinterpret_cast<const uint4*>(featl + (size_t)s * 32);
            acc[0] = __hadd2(acc[0], *(__nv_bfloat162*)&v.x);
            acc[1] = __hadd2(acc[1], *(__nv_bfloat162*)&v.y);
            acc[2] = __hadd2(acc[2], *(__nv_bfloat162*)&v.z);
            acc[3] = __hadd2(acc[3], *(__nv_bfloat162*)&v.w);
        }
    }

    // cross-group reduce in packed bf16x2 (lanes differing in bits 3,4)
    #pragma unroll
    for (int q = 0; q < 4; q++) {
        unsigned int u = *reinterpret_cast<unsigned int*>(&acc[q]);
        unsigned int o = __shfl_xor_sync(0xffffffffu, u, 8);
        acc[q] = __hadd2(acc[q], *reinterpret_cast<__nv_bfloat162*>(&o));
        u = *reinterpret_cast<unsigned int*>(&acc[q]);
        o = __shfl_xor_sync(0xffffffffu, u, 16);
        acc[q] = __hadd2(acc[q], *reinterpret_cast<__nv_bfloat162*>(&o));
    }
    if (grp == 0) {
        *reinterpret_cast<uint4*>(aggr + (size_t)node * 32 + sub * 4) =
            *reinterpret_cast<uint4*>(acc);
    }
}

// ---------------- tensor-core GEMM: act([A1|A2] @ (Whi+Wlo) + b) ---------------------
// Block: 64 rows x 64 cols, 128 threads (4 warps, 16 rows each). K = 128 (8 k-steps),
// mma.sync.m16n8k16 bf16, weights hi+lo split. 48KB static smem (best measured shape).
// mode 0: write relu(out). mode 1: fused collapsed layer-3 reduction + last-block
//         final writeout.
__global__ void __launch_bounds__(128) mma_gemm_kernel(
    const __nv_bfloat162* __restrict__ A1, const __nv_bfloat162* __restrict__ A2,
    const __nv_bfloat16* __restrict__ Whi, const __nv_bfloat16* __restrict__ Wlo,
    const float* __restrict__ bias, __nv_bfloat162* __restrict__ out,
    const int* __restrict__ outdeg, const float* __restrict__ wrel3,
    const float* __restrict__ wroot3, double* __restrict__ red,
    unsigned int* __restrict__ cnt, const float* __restrict__ b3,
    float* __restrict__ final_out, int mode) {
    __shared__ __align__(16) __nv_bfloat16 Ash[64 * 128];        // 16KB
    __shared__ __align__(16) __nv_bfloat16 Wsh[2][128 * 64];     // 32KB (total = 48KB)

    const int tid = threadIdx.x;
    const int lane = tid & 31;
    const int warp = tid >> 5;
    const int row_base = blockIdx.x * 64;

    // load A tile: 64 rows x 128 k (A1 k0-63 chunks0-7, A2 k64-127 chunks8-15)
    {
        int r = tid & 63;
        int half = tid >> 6;
        int grow = row_base + r;
        if (grow >= N_NODES) grow = N_NODES - 1;
        const uint4* src = reinterpret_cast<const uint4*>(
            (half ? A2 : A1) + (size_t)grow * 32);
        #pragma unroll
        for (int q = 0; q < 8; q++) {
            uint4 v = src[q];
            int chunk = half * 8 + q;
            int sw = (chunk & 8) | ((chunk ^ r) & 7);
            *reinterpret_cast<uint4*>(Ash + r * 128 + sw * 8) = v;
        }
    }
    // load W hi/lo: 2 x 128 rows x 8 chunks
    {
        #pragma unroll
        for (int q = 0; q < 16; q++) {
            int lin = q * 128 + tid;             // 0..2047
            int hl = lin >> 10;
            int rem = lin & 1023;
            int r = rem >> 3;
            int c = rem & 7;
            uint4 v = reinterpret_cast<const uint4*>((hl ? Wlo : Whi) + r * 64)[c];
            int sw = c ^ (r & 7);
            *reinterpret_cast<uint4*>(Wsh[hl] + r * 64 + sw * 8) = v;
        }
    }
    __syncthreads();

    float d[8][4];
    #pragma unroll
    for (int t = 0; t < 8; t++)
        #pragma unroll
        for (int q = 0; q < 4; q++) d[t][q] = 0.f;

    const int wrow = warp * 16;

    #pragma unroll
    for (int ks = 0; ks < 8; ks++) {
        uint32_t a0, a1, a2, a3;
        {
            int ar = wrow + (lane & 15);
            int ac = ks * 2 + (lane >> 4);
            int sw = (ac & 8) | ((ac ^ ar) & 7);
            uint32_t addr = su32(Ash + ar * 128 + sw * 8);
            asm volatile("ldmatrix.sync.aligned.m8n8.x4.shared.b16 {%0,%1,%2,%3}, [%4];"
                         : "=r"(a0), "=r"(a1), "=r"(a2), "=r"(a3) : "r"(addr));
        }
        #pragma unroll
        for (int hl = 0; hl < 2; hl++) {
            #pragma unroll
            for (int nt2 = 0; nt2 < 4; nt2++) {
                int krow = ks * 16 + (lane & 15);
                int c = nt2 * 2 + (lane >> 4);
                int sw = c ^ (krow & 7);
                uint32_t addr = su32(Wsh[hl] + krow * 64 + sw * 8);
                uint32_t b0, b1, b2, b3r;
                asm volatile("ldmatrix.sync.aligned.m8n8.x4.trans.shared.b16 {%0,%1,%2,%3}, [%4];"
                             : "=r"(b0), "=r"(b1), "=r"(b2), "=r"(b3r) : "r"(addr));
                asm volatile("mma.sync.aligned.m16n8k16.row.col.f32.bf16.bf16.f32 "
                             "{%0,%1,%2,%3},{%4,%5,%6,%7},{%8,%9},{%0,%1,%2,%3};"
                             : "+f"(d[nt2 * 2][0]), "+f"(d[nt2 * 2][1]),
                               "+f"(d[nt2 * 2][2]), "+f"(d[nt2 * 2][3])
                             : "r"(a0), "r"(a1), "r"(a2), "r"(a3), "r"(b0), "r"(b1));
                asm volatile("mma.sync.aligned.m16n8k16.row.col.f32.bf16.bf16.f32 "
                             "{%0,%1,%2,%3},{%4,%5,%6,%7},{%8,%9},{%0,%1,%2,%3};"
                             : "+f"(d[nt2 * 2 + 1][0]), "+f"(d[nt2 * 2 + 1][1]),
                               "+f"(d[nt2 * 2 + 1][2]), "+f"(d[nt2 * 2 + 1][3])
                             : "r"(a0), "r"(a1), "r"(a2), "r"(a3), "r"(b2), "r"(b3r));
            }
        }
    }

    const int g = lane >> 2;
    const int tg = lane & 3;
    const int row0 = row_base + wrow + g;
    const int row1 = row0 + 8;

    if (mode == 0) {
        #pragma unroll
        for (int t = 0; t < 8; t++) {
            int col = 8 * t + 2 * tg;
            float2 bv = *reinterpret_cast<const float2*>(bias + col);
            float o0 = fmaxf(d[t][0] + bv.x, 0.f), o1 = fmaxf(d[t][1] + bv.y, 0.f);
            float o2 = fmaxf(d[t][2] + bv.x, 0.f), o3 = fmaxf(d[t][3] + bv.y, 0.f);
            if (row0 < N_NODES)
                out[(size_t)row0 * 32 + (col >> 1)] = __float22bfloat162_rn(make_float2(o0, o1));
            if (row1 < N_NODES)
                out[(size_t)row1 * 32 + (col >> 1)] = __float22bfloat162_rn(make_float2(o2, o3));
        }
    } else {
        // fused collapsed layer-3: sum_i outdeg[i]*(h2_i . wrel3) + (h2_i . wroot3)
        float r0rel = 0.f, r0root = 0.f, r1rel = 0.f, r1root = 0.f;
        #pragma unroll
        for (int t = 0; t < 8; t++) {
            int col = 8 * t + 2 * tg;
            float2 bv = *reinterpret_cast<const float2*>(bias + col);
            float o0 = fmaxf(d[t][0] + bv.x, 0.f), o1 = fmaxf(d[t][1] + bv.y, 0.f);
            float o2 = fmaxf(d[t][2] + bv.x, 0.f), o3 = fmaxf(d[t][3] + bv.y, 0.f);
            float2 wr = *reinterpret_cast<const float2*>(wrel3 + col);
            float2 wo = *reinterpret_cast<const float2*>(wroot3 + col);
            r0rel  += o0 * wr.x + o1 * wr.y;
            r0root += o0 * wo.x + o1 * wo.y;
            r1rel  += o2 * wr.x + o3 * wr.y;
            r1root += o2 * wo.x + o3 * wo.y;
        }
        #pragma unroll
        for (int off = 1; off <= 2; off <<= 1) {
            r0rel  += __shfl_xor_sync(0xffffffffu, r0rel,  off);
            r0root += __shfl_xor_sync(0xffffffffu, r0root, off);
            r1rel  += __shfl_xor_sync(0xffffffffu, r1rel,  off);
            r1root += __shfl_xor_sync(0xffffffffu, r1root, off);
        }
        float val = 0.f;
        if (tg == 0) {
            if (row0 < N_NODES) val += (float)__ldg(outdeg + row0) * r0rel + r0root;
            if (row1 < N_NODES) val += (float)__ldg(outdeg + row1) * r1rel + r1root;
        }
        val += __shfl_xor_sync(0xffffffffu, val, 4);
        val += __shfl_xor_sync(0xffffffffu, val, 8);
        val += __shfl_xor_sync(0xffffffffu, val, 16);
        if (lane == 0) atomicAdd(red, (double)val);

        // last-block final writeout
        __syncthreads();
        if (tid == 0) {
            __threadfence();
            unsigned int old = atomicInc(cnt, 0xffffffffu);
            if (old == (unsigned int)(gridDim.x - 1)) {
                double r = atomicAdd(red, 0.0);   // all contributions visible
                final_out[0] = (float)(r / (double)N_NODES + (double)b3[0]);
            }
        }
    }
}

// ---------------- launch ----------------
extern "C" void kernel_launch(void* const* d_in, const int* in_sizes, int n_in,
                              void* d_out, int out_size) {
    const float* x      = (const float*)d_in[0];
    const void*  ei     = d_in[1];
    const float* wrel1  = (const float*)d_in[2];
    const float* brel1  = (const float*)d_in[3];
    const float* wroot1 = (const float*)d_in[4];
    const float* wrel2  = (const float*)d_in[5];
    const float* brel2  = (const float*)d_in[6];
    const float* wroot2 = (const float*)d_in[7];
    const float* wrel3  = (const float*)d_in[8];
    const float* brel3  = (const float*)d_in[9];
    const float* wroot3 = (const float*)d_in[10];
    float* out = (float*)d_out;

    __nv_bfloat162 *xbf, *aggr, *h1;
    __nv_bfloat16 *whi, *wlo;
    int *csr, *indeg, *outdeg, *rowtmp, *rowptr, *cursor, *bsum, *is64;
    double* red;
    unsigned int* cnt;
    cudaGetSymbolAddress((void**)&xbf,    g_xbf);
    cudaGetSymbolAddress((void**)&aggr,   g_aggr);
    cudaGetSymbolAddress((void**)&h1,     g_h1);
    cudaGetSymbolAddress((void**)&whi,    g_whi);
    cudaGetSymbolAddress((void**)&wlo,    g_wlo);
    cudaGetSymbolAddress((void**)&csr,    g_csr);
    cudaGetSymbolAddress((void**)&indeg,  g_indeg);
    cudaGetSymbolAddress((void**)&outdeg, g_outdeg);
    cudaGetSymbolAddress((void**)&rowtmp, g_rowtmp);
    cudaGetSymbolAddress((void**)&rowptr, g_rowptr);
    cudaGetSymbolAddress((void**)&cursor, g_cursor);
    cudaGetSymbolAddress((void**)&bsum,   g_bsum);
    cudaGetSymbolAddress((void**)&red,    g_red);
    cudaGetSymbolAddress((void**)&cnt,    g_cnt);
    cudaGetSymbolAddress((void**)&is64,   g_is64);

    const int eblk = (N_EDGES + 255) / 256;     // 6250
    const int nblk = (N_NODES + 255) / 256;     // 391
    const int ablk = (N_NODES + 7) / 8;         // 12500

    // prep + CSR build (R10 structure — measured fastest)
    detect_zero_kernel<<<nblk, 256>>>((const unsigned int*)ei, is64, indeg, outdeg, red, cnt);
    histconv_kernel<<<eblk, 256>>>(ei, x, xbf, indeg, outdeg, is64,
                                   wrel1, wroot1, wrel2, wroot2, whi, wlo);
    scan1_kernel<<<SCAN_BLOCKS, 512>>>(indeg, rowtmp, bsum);
    scan23_kernel<<<nblk, 256>>>(rowtmp, bsum, indeg, rowptr, cursor);
    fill_kernel<<<eblk, 256>>>(ei, cursor, csr, is64);

    // layer 1
    aggr_kernel<<<ablk, 256>>>(xbf, aggr, rowptr, csr);
    mma_gemm_kernel<<<GBLK, 128>>>(aggr, xbf, whi, wlo, brel1, h1,
                                   nullptr, nullptr, nullptr, nullptr, nullptr,
                                   nullptr, nullptr, 0);
    // layer 2 (+ fused collapsed layer-3 reduction + last-block final writeout)
    aggr_kernel<<<ablk, 256>>>(h1, aggr, rowptr, csr);
    mma_gemm_kernel<<<GBLK, 128>>>(aggr, h1, whi + 8192, wlo + 8192, brel2, nullptr,
                                   outdeg, wrel3, wroot3, red, cnt, brel3, out, 1);
}